// round 13
// baseline (speedup 1.0000x reference)
#include <cuda_runtime.h>
#include <cuda_bf16.h>
#include <cstdint>
#include <cfloat>

#define NPTS   16384
#define PCLOUD 2048
#define BCLOUD 8
#define DIN    128
#define KNBR   32
#define HID    256
#define DOUT   256
#define R2     0.04f

// ---------------- scratch (no cudaMalloc allowed) ----------------
__device__ float g_Z[NPTS * HID];          // Z = x @ W1[0:128]  (fp32, no bias)
__device__ int   g_idx[NPTS * KNBR];       // neighbor indices (global row ids)
__device__ int   g_cnt[NPTS];              // valid neighbor counts (<=K)

// ---------------- helpers ----------------
__device__ __forceinline__ void ffma2(unsigned long long& d,
                                      unsigned long long a,
                                      unsigned long long b) {
    asm("fma.rn.f32x2 %0, %1, %2, %0;" : "+l"(d) : "l"(a), "l"(b));
}
__device__ __forceinline__ unsigned long long packf2(float lo, float hi) {
    unsigned long long r;
    asm("mov.b64 %0, {%1, %2};" : "=l"(r) : "f"(lo), "f"(hi));
    return r;
}
__device__ __forceinline__ void unpackf2(float& lo, float& hi, unsigned long long v) {
    asm("mov.b64 {%0, %1}, %2;" : "=f"(lo), "=f"(hi) : "l"(v));
}
__device__ __forceinline__ void cp_async16(uint32_t saddr, const void* gptr) {
    asm volatile("cp.async.cg.shared.global [%0], [%1], 16;" :: "r"(saddr), "l"(gptr));
}
__device__ __forceinline__ void cp_commit() { asm volatile("cp.async.commit_group;"); }
__device__ __forceinline__ void cp_wait1()  { asm volatile("cp.async.wait_group 1;"); }
__device__ __forceinline__ void cp_wait0()  { asm volatile("cp.async.wait_group 0;"); }

// ---------------- kernel 1: ball query ----------------
// d2 = (n2_i + n2_j) - 2*dot with:
//   n2  = ((x*x + y*y) + z*z)   -- squares rounded, sequential adds
//   dot = fma(z_i,z_j, fma(y_i,y_j, rn(x_i*x_j)))  -- GEMM FFMA-chain semantics
// This combination produced BIT-EXACT Output 0 in rounds 8 and 12. Do not touch.
__global__ void __launch_bounds__(256) ball_query_kernel(const float* __restrict__ pos) {
    __shared__ float sp[PCLOUD * 3];    // raw fp32 coords
    __shared__ float sn2[PCLOUD];       // fp32 n2 from raw coords

    const int blocksPerCloud = PCLOUD / 8;             // 256
    const int cloud = blockIdx.x / blocksPerCloud;
    const int base  = cloud * PCLOUD;

    for (int t = threadIdx.x; t < PCLOUD; t += 256) {
        float x = pos[(base + t) * 3 + 0];
        float y = pos[(base + t) * 3 + 1];
        float z = pos[(base + t) * 3 + 2];
        sp[t * 3 + 0] = x; sp[t * 3 + 1] = y; sp[t * 3 + 2] = z;
        sn2[t] = __fadd_rn(__fadd_rn(__fmul_rn(x, x), __fmul_rn(y, y)), __fmul_rn(z, z));
    }
    __syncthreads();

    const int warp = threadIdx.x >> 5;
    const int lane = threadIdx.x & 31;
    const int il   = (blockIdx.x % blocksPerCloud) * 8 + warp;  // local point index
    const int i    = base + il;

    const float xi = sp[il * 3 + 0], yi = sp[il * 3 + 1], zi = sp[il * 3 + 2];
    const float n2i = sn2[il];

    int cnt = 0;
    for (int jb = 0; jb < PCLOUD / 32 && cnt < KNBR; jb++) {
        const int jl = jb * 32 + lane;
        float dot = __fmul_rn(xi, sp[jl * 3 + 0]);
        dot = __fmaf_rn(yi, sp[jl * 3 + 1], dot);
        dot = __fmaf_rn(zi, sp[jl * 3 + 2], dot);
        float d2 = __fsub_rn(__fadd_rn(n2i, sn2[jl]), __fmul_rn(2.0f, dot));
        bool within = (d2 <= R2);
        unsigned m = __ballot_sync(0xffffffffu, within);
        if (within) {
            int rank = cnt + __popc(m & ((1u << lane) - 1u));
            if (rank < KNBR) g_idx[i * KNBR + rank] = base + jl;
        }
        cnt += __popc(m);
    }
    if (lane == 0) g_cnt[i] = cnt < KNBR ? cnt : KNBR;
}

// ---------------- kernel 2: Z = x @ W1[0:128,:]  (fp32 exact, no bias) ----------------
__global__ void __launch_bounds__(256) z_kernel(const float* __restrict__ x,
                                                const float* __restrict__ W1) {
    __shared__ __align__(16) float sin_[16][128];
    const int r0 = blockIdx.x * 16;

    for (int t = threadIdx.x; t < 16 * 128; t += 256) {
        int r = t >> 7, f = t & 127;
        sin_[r][f] = x[(r0 + r) * DIN + f];
    }
    __syncthreads();

    const int o = threadIdx.x;
    float acc[16];
#pragma unroll
    for (int r = 0; r < 16; r++) acc[r] = 0.0f;

    for (int f4 = 0; f4 < 32; f4++) {
        const float w0 = W1[(f4 * 4 + 0) * HID + o];
        const float w1 = W1[(f4 * 4 + 1) * HID + o];
        const float w2 = W1[(f4 * 4 + 2) * HID + o];
        const float w3 = W1[(f4 * 4 + 3) * HID + o];
#pragma unroll
        for (int r = 0; r < 16; r++) {
            float4 v = *reinterpret_cast<const float4*>(&sin_[r][f4 * 4]);
            acc[r] += v.x * w0;
            acc[r] += v.y * w1;
            acc[r] += v.z * w2;
            acc[r] += v.w * w3;
        }
    }
#pragma unroll
    for (int r = 0; r < 16; r++) g_Z[(r0 + r) * HID + o] = acc[r];
}

// ---------------- kernel 3: fused h1-build + GEMM2 + maxpool ----------------
#define WBUF_OFF 0
#define H1_OFF   32768
#define RED_OFF  (32768 + 17408)
#define W1B_OFF  (RED_OFF + 2048)
#define B1_OFF   (W1B_OFF + 768)
#define POSJ_OFF (B1_OFF + 256)
#define PIS_OFF  (POSJ_OFF + 192)
#define IDX_OFF  (PIS_OFF + 8)
#define SMEM_MAIN_FLOATS (IDX_OFF + 68)
#define SMEM_MAIN_BYTES  (SMEM_MAIN_FLOATS * 4)

__global__ void __launch_bounds__(512, 1) fused_kernel(const float* __restrict__ pos,
                                                       const float* __restrict__ W1,
                                                       const float* __restrict__ W2,
                                                       const float* __restrict__ b1,
                                                       const float* __restrict__ b2,
                                                       float* __restrict__ out) {
    extern __shared__ float smem[];
    float* wbuf  = smem + WBUF_OFF;                 // [2][64*256]
    float* h1s   = smem + H1_OFF;                   // [2][256][34]
    float* red   = smem + RED_OFF;                  // [2][4][256]
    float* w1b   = smem + W1B_OFF;                  // [3][256]
    float* b1s   = smem + B1_OFF;                   // [256]
    float* posj  = smem + POSJ_OFF;                 // [2][32][3]
    float* pis   = smem + PIS_OFF;                  // [2][4]
    int*   sidx  = (int*)(smem + IDX_OFF);          // [2][32]
    int*   scnt  = sidx + 2 * KNBR;                 // [2]

    const int tid = threadIdx.x;
    const int p   = tid >> 8;        // point within block (0/1)
    const int t   = tid & 255;       // lane within point
    const int i   = blockIdx.x * 2 + p;

    if (tid < 2 * KNBR) sidx[tid] = g_idx[(blockIdx.x * 2 + (tid >> 5)) * KNBR + (tid & 31)];
    if (tid >= 64 && tid < 66) scnt[tid - 64] = g_cnt[blockIdx.x * 2 + (tid - 64)];
    if (tid >= 66 && tid < 72) {
        int pp = (tid - 66) / 3, d = (tid - 66) % 3;
        pis[pp * 4 + d] = pos[(blockIdx.x * 2 + pp) * 3 + d];
    }
    for (int c = tid; c < 768; c += 512) w1b[c] = W1[128 * HID + c];
    if (tid < 256) b1s[tid] = b1[tid];

    // kick off W2 quarter 0 copy
    {
        uint32_t sdst = (uint32_t)__cvta_generic_to_shared(wbuf);
        const float* src = W2;
        for (int c = tid; c < 64 * 256 / 4; c += 512)
            cp_async16(sdst + c * 16, src + c * 4);
        cp_commit();
    }
    __syncthreads();

    // neighbor coords to smem (raw fp32)
    if (tid < 192) {
        int pp = tid / 96, r = tid % 96, k = r / 3, d = r % 3;
        posj[tid] = pos[sidx[pp * KNBR + k] * 3 + d];
    }
    __syncthreads();

    const int cnt = scnt[p];
    const float pix = pis[p * 4 + 0], piy = pis[p * 4 + 1], piz = pis[p * 4 + 2];
    const float w128 = w1b[0 * 256 + t], w129 = w1b[1 * 256 + t], w130 = w1b[2 * 256 + t];
    const float b1t = b1s[t];

    // build h1[p][h=t][k] = relu( (Z[j][t] + rel@W1b) + b1 )   (fp32 exact)
    {
        float* h1p = h1s + p * 256 * 34 + t * 34;
#pragma unroll 4
        for (int k = 0; k < KNBR; k++) {
            float v = 0.0f;
            if (k < cnt) {
                int j = sidx[p * KNBR + k];
                float rx = __fsub_rn(posj[(p * 32 + k) * 3 + 0], pix);
                float ry = __fsub_rn(posj[(p * 32 + k) * 3 + 1], piy);
                float rz = __fsub_rn(posj[(p * 32 + k) * 3 + 2], piz);
                float acc = g_Z[j * HID + t];
                acc = fmaf(rx, w128, acc);
                acc = fmaf(ry, w129, acc);
                acc = fmaf(rz, w130, acc);
                acc = __fadd_rn(acc, b1t);
                v = fmaxf(acc, 0.0f);
            }
            h1p[k] = v;
        }
    }
    __syncthreads();

    // GEMM2 mapping: tk in 0..3 owns k = tk*8..tk*8+7 ; oc in 0..63 ; o = oc + 64*m
    const int tk = t >> 6;
    const int oc = t & 63;
    unsigned long long acc[4][4];
#pragma unroll
    for (int m = 0; m < 4; m++)
#pragma unroll
        for (int q = 0; q < 4; q++) acc[m][q] = 0ull;

    const unsigned long long* h1pair =
        reinterpret_cast<const unsigned long long*>(h1s + p * 256 * 34);

    for (int quarter = 0; quarter < 4; quarter++) {
        if (quarter < 3) {
            float* dst = wbuf + ((quarter + 1) & 1) * (64 * 256);
            uint32_t sdst = (uint32_t)__cvta_generic_to_shared(dst);
            const float* src = W2 + (quarter + 1) * 64 * 256;
            for (int c = tid; c < 64 * 256 / 4; c += 512)
                cp_async16(sdst + c * 16, src + c * 4);
            cp_commit();
            cp_wait1();
        } else {
            cp_wait0();
        }
        __syncthreads();

        const float* wq = wbuf + (quarter & 1) * (64 * 256);
        const int hbase = quarter * 64;
#pragma unroll 2
        for (int hh = 0; hh < 64; hh++) {
            const unsigned long long* hp = h1pair + (hbase + hh) * 17 + tk * 4;
            unsigned long long a0 = hp[0], a1 = hp[1], a2 = hp[2], a3 = hp[3];
            const float* wr = wq + hh * 256 + oc;
            unsigned long long w0 = packf2(wr[0],   wr[0]);
            unsigned long long w1 = packf2(wr[64],  wr[64]);
            unsigned long long w2 = packf2(wr[128], wr[128]);
            unsigned long long w3 = packf2(wr[192], wr[192]);
            ffma2(acc[0][0], a0, w0); ffma2(acc[0][1], a1, w0);
            ffma2(acc[0][2], a2, w0); ffma2(acc[0][3], a3, w0);
            ffma2(acc[1][0], a0, w1); ffma2(acc[1][1], a1, w1);
            ffma2(acc[1][2], a2, w1); ffma2(acc[1][3], a3, w1);
            ffma2(acc[2][0], a0, w2); ffma2(acc[2][1], a1, w2);
            ffma2(acc[2][2], a2, w2); ffma2(acc[2][3], a3, w2);
            ffma2(acc[3][0], a0, w3); ffma2(acc[3][1], a1, w3);
            ffma2(acc[3][2], a2, w3); ffma2(acc[3][3], a3, w3);
        }
        __syncthreads();
    }

    // per-thread max over owned valid k, then cross-tk reduction in smem
#pragma unroll
    for (int m = 0; m < 4; m++) {
        float best = -FLT_MAX;
#pragma unroll
        for (int q = 0; q < 4; q++) {
            float lo, hi;
            unpackf2(lo, hi, acc[m][q]);
            int k0 = tk * 8 + 2 * q;
            if (k0 < cnt)     best = fmaxf(best, lo);
            if (k0 + 1 < cnt) best = fmaxf(best, hi);
        }
        red[(p * 4 + tk) * 256 + oc + 64 * m] = best;
    }
    __syncthreads();

    {
        float v = red[(p * 4 + 0) * 256 + t];
        v = fmaxf(v, red[(p * 4 + 1) * 256 + t]);
        v = fmaxf(v, red[(p * 4 + 2) * 256 + t]);
        v = fmaxf(v, red[(p * 4 + 3) * 256 + t]);
        v = __fadd_rn(v, b2[t]);
        v = fmaxf(v, 0.0f);
        out[i * DOUT + t] = v;
    }
}

// ---------------- extras: pass-through outputs (pos, batch) ----------------
// d_out is a single FLOAT32 buffer of out_size elements:
//   [0, NPTS*DOUT)                : out
//   [NPTS*DOUT, +NPTS*3)          : pos (float32)
//   [NPTS*DOUT+NPTS*3, +NPTS)     : float32(batch)
// batch INPUT is int32 (JAX x64 disabled downcasts int64 -> int32).
__global__ void extras_kernel(const float* __restrict__ pos,
                              const int* __restrict__ batch,
                              float* __restrict__ out) {
    int t = blockIdx.x * 256 + threadIdx.x;
    if (t < NPTS * 3) out[NPTS * DOUT + t] = pos[t];
    if (t < NPTS)     out[NPTS * DOUT + NPTS * 3 + t] = (float)batch[t];
}

// ---------------- launch ----------------
extern "C" void kernel_launch(void* const* d_in, const int* in_sizes, int n_in,
                              void* d_out, int out_size) {
    const float* x     = (const float*)d_in[0];
    const float* pos   = (const float*)d_in[1];
    const int*   batch = (const int*)d_in[2];     // int32 (x64-off JAX)
    const float* W1    = (const float*)d_in[3];
    const float* b1    = (const float*)d_in[4];
    const float* W2    = (const float*)d_in[5];
    const float* b2    = (const float*)d_in[6];
    float* out = (float*)d_out;

    cudaFuncSetAttribute(fused_kernel, cudaFuncAttributeMaxDynamicSharedMemorySize,
                         SMEM_MAIN_BYTES);

    ball_query_kernel<<<NPTS / 8, 256>>>(pos);
    z_kernel<<<NPTS / 16, 256>>>(x, W1);
    fused_kernel<<<NPTS / 2, 512, SMEM_MAIN_BYTES>>>(pos, W1, W2, b1, b2, out);

    if (out_size > NPTS * DOUT)
        extras_kernel<<<(NPTS * 3 + 255) / 256, 256>>>(pos, batch, out);
}

// round 16
// speedup vs baseline: 1.1785x; 1.1785x over previous
#include <cuda_runtime.h>
#include <cuda_bf16.h>
#include <cstdint>
#include <cfloat>

#define NPTS   16384
#define PCLOUD 2048
#define DIN    128
#define KNBR   32
#define HID    256
#define DOUT   256
#define R2     0.04f

// ---------------- scratch ----------------
__device__ float g_Z[NPTS * HID];              // Z = x @ W1[0:128] (fp32 exact)
__device__ int   g_idx[NPTS * KNBR];
__device__ int   g_cnt[NPTS];
// W2^T split to bf16 hi/lo, stored [o][h] row-major (o-major for B fragments)
__device__ __nv_bfloat16 g_Bhi[DOUT * HID];
__device__ __nv_bfloat16 g_Blo[DOUT * HID];

// ---------------- helpers ----------------
__device__ __forceinline__ void cp_async16(uint32_t saddr, const void* gptr) {
    asm volatile("cp.async.cg.shared.global [%0], [%1], 16;" :: "r"(saddr), "l"(gptr));
}
__device__ __forceinline__ void cp_commit() { asm volatile("cp.async.commit_group;"); }
__device__ __forceinline__ void cp_wait0()  { asm volatile("cp.async.wait_group 0;"); }

// m16n8k16 row.col f32.bf16.bf16.f32 (base PTX, sm_80+; HMMA on Blackwell)
__device__ __forceinline__ void mma16816(float* d, const uint32_t* a, const uint32_t* b) {
    asm volatile(
        "mma.sync.aligned.m16n8k16.row.col.f32.bf16.bf16.f32 "
        "{%0,%1,%2,%3}, {%4,%5,%6,%7}, {%8,%9}, {%0,%1,%2,%3};"
        : "+f"(d[0]), "+f"(d[1]), "+f"(d[2]), "+f"(d[3])
        : "r"(a[0]), "r"(a[1]), "r"(a[2]), "r"(a[3]), "r"(b[0]), "r"(b[1]));
}

// ---------------- kernel 1: ball query (bit-exact, DO NOT TOUCH) ----------------
__global__ void __launch_bounds__(256) ball_query_kernel(const float* __restrict__ pos) {
    __shared__ float sp[PCLOUD * 3];
    __shared__ float sn2[PCLOUD];

    const int blocksPerCloud = PCLOUD / 8;
    const int cloud = blockIdx.x / blocksPerCloud;
    const int base  = cloud * PCLOUD;

    for (int t = threadIdx.x; t < PCLOUD; t += 256) {
        float x = pos[(base + t) * 3 + 0];
        float y = pos[(base + t) * 3 + 1];
        float z = pos[(base + t) * 3 + 2];
        sp[t * 3 + 0] = x; sp[t * 3 + 1] = y; sp[t * 3 + 2] = z;
        sn2[t] = __fadd_rn(__fadd_rn(__fmul_rn(x, x), __fmul_rn(y, y)), __fmul_rn(z, z));
    }
    __syncthreads();

    const int warp = threadIdx.x >> 5;
    const int lane = threadIdx.x & 31;
    const int il   = (blockIdx.x % blocksPerCloud) * 8 + warp;
    const int i    = base + il;

    const float xi = sp[il * 3 + 0], yi = sp[il * 3 + 1], zi = sp[il * 3 + 2];
    const float n2i = sn2[il];

    int cnt = 0;
    for (int jb = 0; jb < PCLOUD / 32 && cnt < KNBR; jb++) {
        const int jl = jb * 32 + lane;
        float dot = __fmul_rn(xi, sp[jl * 3 + 0]);
        dot = __fmaf_rn(yi, sp[jl * 3 + 1], dot);
        dot = __fmaf_rn(zi, sp[jl * 3 + 2], dot);
        float d2 = __fsub_rn(__fadd_rn(n2i, sn2[jl]), __fmul_rn(2.0f, dot));
        bool within = (d2 <= R2);
        unsigned m = __ballot_sync(0xffffffffu, within);
        if (within) {
            int rank = cnt + __popc(m & ((1u << lane) - 1u));
            if (rank < KNBR) g_idx[i * KNBR + rank] = base + jl;
        }
        cnt += __popc(m);
    }
    if (lane == 0) g_cnt[i] = cnt < KNBR ? cnt : KNBR;
}

// ---------------- kernel 2: Z = x @ W1[0:128,:] (fp32 exact) ----------------
__global__ void __launch_bounds__(256) z_kernel(const float* __restrict__ x,
                                                const float* __restrict__ W1) {
    __shared__ __align__(16) float sin_[16][128];
    const int r0 = blockIdx.x * 16;

    for (int t = threadIdx.x; t < 16 * 128; t += 256) {
        int r = t >> 7, f = t & 127;
        sin_[r][f] = x[(r0 + r) * DIN + f];
    }
    __syncthreads();

    const int o = threadIdx.x;
    float acc[16];
#pragma unroll
    for (int r = 0; r < 16; r++) acc[r] = 0.0f;

    for (int f4 = 0; f4 < 32; f4++) {
        const float w0 = W1[(f4 * 4 + 0) * HID + o];
        const float w1 = W1[(f4 * 4 + 1) * HID + o];
        const float w2 = W1[(f4 * 4 + 2) * HID + o];
        const float w3 = W1[(f4 * 4 + 3) * HID + o];
#pragma unroll
        for (int r = 0; r < 16; r++) {
            float4 v = *reinterpret_cast<const float4*>(&sin_[r][f4 * 4]);
            acc[r] += v.x * w0;
            acc[r] += v.y * w1;
            acc[r] += v.z * w2;
            acc[r] += v.w * w3;
        }
    }
#pragma unroll
    for (int r = 0; r < 16; r++) g_Z[(r0 + r) * HID + o] = acc[r];
}

// ---------------- kernel 0b: split W2^T into bf16 hi/lo, [o][h] ----------------
__global__ void __launch_bounds__(256) prep_kernel(const float* __restrict__ W2) {
    int t = blockIdx.x * 256 + threadIdx.x;      // [0, 65536)
    int o = t >> 8, h = t & 255;
    float w = W2[h * DOUT + o];
    __nv_bfloat16 hi = __float2bfloat16(w);
    __nv_bfloat16 lo = __float2bfloat16(__fsub_rn(w, __bfloat162float(hi)));
    g_Bhi[o * HID + h] = hi;
    g_Blo[o * HID + h] = lo;
}

// ---------------- kernel 3: fused h1-build + HMMA GEMM2 + maxpool ----------------
// 4 points/block (128 edge rows), 512 threads = 16 warps (4 warp_m x 4 warp_n).
// A (h1 hi/lo): [128 rows][264 bf16] padded (132 words/row; 132 % 32 == 4).
// B chunk: [64 o-rows][264 bf16] padded, hi + lo.
#define A_HI_B   0
#define A_LO_B   67584
#define B_HI_B   135168
#define B_LO_B   168960
#define W1B_B    202752
#define B1_B     205824
#define SMEM_FUSED_BYTES (205824 + 1024)
#define ASTRIDE  132    // words per A/B row

__global__ void __launch_bounds__(512, 1) fused_kernel(const float* __restrict__ pos,
                                                       const float* __restrict__ W1,
                                                       const float* __restrict__ b1,
                                                       const float* __restrict__ b2,
                                                       float* __restrict__ out) {
    extern __shared__ __align__(16) unsigned char smem[];
    const uint32_t smem_u32 = (uint32_t)__cvta_generic_to_shared(smem);

    const int tid  = threadIdx.x;
    const int wid  = tid >> 5;
    const int lane = tid & 31;
    const int i0   = blockIdx.x * 4;
    const int warp_m = wid >> 2;        // point within block
    const int warp_n = wid & 3;         // 16-col group within 64-col chunk

    float* w1b = (float*)(smem + W1B_B);
    float* b1s = (float*)(smem + B1_B);

    // issue B chunk 0 loads (overlap with A build)
    {
        for (int idx = tid; idx < 64 * 32; idx += 512) {
            int row = idx >> 5, u = idx & 31;
            cp_async16(smem_u32 + B_HI_B + row * 528 + u * 16,
                       (const char*)g_Bhi + row * 512 + u * 16);
            cp_async16(smem_u32 + B_LO_B + row * 528 + u * 16,
                       (const char*)g_Blo + row * 512 + u * 16);
        }
        cp_commit();
    }
    for (int c = tid; c < 768; c += 512) w1b[c] = W1[128 * HID + c];
    if (tid < 256) b1s[tid] = b1[tid];
    __syncthreads();

    // phase 1: build A = h1 bf16 hi/lo.  thread -> edge e = tid>>2, h-quarter hq = tid&3.
    {
        const int e  = tid >> 2;
        const int hq = tid & 3;
        const int p  = e >> 5, k = e & 31;
        const int i  = i0 + p;
        const int cnt = g_cnt[i];
        const int hbase = hq * 64;
        const uint32_t rowbase = (uint32_t)e * 528 + (uint32_t)hq * 128;

        if (k < cnt) {
            const int j = g_idx[i * KNBR + k];
            const float rx = __fsub_rn(pos[j * 3 + 0], pos[i * 3 + 0]);
            const float ry = __fsub_rn(pos[j * 3 + 1], pos[i * 3 + 1]);
            const float rz = __fsub_rn(pos[j * 3 + 2], pos[i * 3 + 2]);
            const float* Zr = g_Z + (size_t)j * HID + hbase;
#pragma unroll
            for (int m4 = 0; m4 < 8; m4++) {
                float4 za = *(const float4*)(Zr + m4 * 8);
                float4 zb = *(const float4*)(Zr + m4 * 8 + 4);
                float vs[8] = {za.x, za.y, za.z, za.w, zb.x, zb.y, zb.z, zb.w};
                uint32_t phi[4], plo[4];
#pragma unroll
                for (int u2 = 0; u2 < 4; u2++) {
                    int h0 = hbase + m4 * 8 + u2 * 2;
                    float v0 = vs[u2 * 2 + 0];
                    v0 = fmaf(rx, w1b[0 * 256 + h0], v0);
                    v0 = fmaf(ry, w1b[1 * 256 + h0], v0);
                    v0 = fmaf(rz, w1b[2 * 256 + h0], v0);
                    v0 = __fadd_rn(v0, b1s[h0]);
                    v0 = fmaxf(v0, 0.0f);
                    float v1 = vs[u2 * 2 + 1];
                    v1 = fmaf(rx, w1b[0 * 256 + h0 + 1], v1);
                    v1 = fmaf(ry, w1b[1 * 256 + h0 + 1], v1);
                    v1 = fmaf(rz, w1b[2 * 256 + h0 + 1], v1);
                    v1 = __fadd_rn(v1, b1s[h0 + 1]);
                    v1 = fmaxf(v1, 0.0f);
                    __nv_bfloat16 h0b = __float2bfloat16(v0);
                    __nv_bfloat16 h1b = __float2bfloat16(v1);
                    __nv_bfloat16 l0b = __float2bfloat16(__fsub_rn(v0, __bfloat162float(h0b)));
                    __nv_bfloat16 l1b = __float2bfloat16(__fsub_rn(v1, __bfloat162float(h1b)));
                    __nv_bfloat162 ph; ph.x = h0b; ph.y = h1b;
                    __nv_bfloat162 pl; pl.x = l0b; pl.y = l1b;
                    phi[u2] = *reinterpret_cast<uint32_t*>(&ph);
                    plo[u2] = *reinterpret_cast<uint32_t*>(&pl);
                }
                *(uint4*)(smem + A_HI_B + rowbase + m4 * 16) = make_uint4(phi[0], phi[1], phi[2], phi[3]);
                *(uint4*)(smem + A_LO_B + rowbase + m4 * 16) = make_uint4(plo[0], plo[1], plo[2], plo[3]);
            }
        } else {
            uint4 z4 = make_uint4(0, 0, 0, 0);
#pragma unroll
            for (int m4 = 0; m4 < 8; m4++) {
                *(uint4*)(smem + A_HI_B + rowbase + m4 * 16) = z4;
                *(uint4*)(smem + A_LO_B + rowbase + m4 * 16) = z4;
            }
        }
    }
    cp_wait0();
    __syncthreads();

    const uint32_t* Ahi32 = (const uint32_t*)(smem + A_HI_B);
    const uint32_t* Alo32 = (const uint32_t*)(smem + A_LO_B);
    const uint32_t* Bhi32 = (const uint32_t*)(smem + B_HI_B);
    const uint32_t* Blo32 = (const uint32_t*)(smem + B_LO_B);

    const int g = lane >> 2, t = lane & 3;
    const int i = i0 + warp_m;
    const int cnt = g_cnt[i];

    for (int chunk = 0; chunk < 4; chunk++) {
        float acc[2][2][4];
#pragma unroll
        for (int mt = 0; mt < 2; mt++)
#pragma unroll
            for (int nt = 0; nt < 2; nt++)
#pragma unroll
                for (int q = 0; q < 4; q++) acc[mt][nt][q] = 0.0f;

        const int r0 = warp_m * 32 + g;
        const int br = warp_n * 16 + g;

#pragma unroll
        for (int s = 0; s < 3; s++) {
            const uint32_t* Ai = (s == 2) ? Alo32 : Ahi32;
            const uint32_t* Bi = (s == 1) ? Blo32 : Bhi32;
#pragma unroll
            for (int ks = 0; ks < 16; ks++) {
                const int kw = ks * 8 + t;
                uint32_t a0[4], a1[4], b0[2], b1[2];
                a0[0] = Ai[(r0)      * ASTRIDE + kw];
                a0[1] = Ai[(r0 + 8)  * ASTRIDE + kw];
                a0[2] = Ai[(r0)      * ASTRIDE + kw + 4];
                a0[3] = Ai[(r0 + 8)  * ASTRIDE + kw + 4];
                a1[0] = Ai[(r0 + 16) * ASTRIDE + kw];
                a1[1] = Ai[(r0 + 24) * ASTRIDE + kw];
                a1[2] = Ai[(r0 + 16) * ASTRIDE + kw + 4];
                a1[3] = Ai[(r0 + 24) * ASTRIDE + kw + 4];
                b0[0] = Bi[(br)     * ASTRIDE + kw];
                b0[1] = Bi[(br)     * ASTRIDE + kw + 4];
                b1[0] = Bi[(br + 8) * ASTRIDE + kw];
                b1[1] = Bi[(br + 8) * ASTRIDE + kw + 4];
                mma16816(acc[0][0], a0, b0);
                mma16816(acc[0][1], a0, b1);
                mma16816(acc[1][0], a1, b0);
                mma16816(acc[1][1], a1, b1);
            }
        }
        __syncthreads();                 // all warps done reading B chunk
        if (chunk < 3) {
            for (int idx = tid; idx < 64 * 32; idx += 512) {
                int row = idx >> 5, u = idx & 31;
                cp_async16(smem_u32 + B_HI_B + row * 528 + u * 16,
                           (const char*)g_Bhi + ((chunk + 1) * 64 + row) * 512 + u * 16);
                cp_async16(smem_u32 + B_LO_B + row * 528 + u * 16,
                           (const char*)g_Blo + ((chunk + 1) * 64 + row) * 512 + u * 16);
            }
            cp_commit();
        }

        // epilogue: warp-local maxpool over 32 edges of point warp_m (mask k>=cnt)
#pragma unroll
        for (int nt = 0; nt < 2; nt++) {
#pragma unroll
            for (int j = 0; j < 2; j++) {
                float v = -FLT_MAX;
                if (g < cnt)      v = fmaxf(v, acc[0][nt][j]);
                if (g + 8 < cnt)  v = fmaxf(v, acc[0][nt][2 + j]);
                if (g + 16 < cnt) v = fmaxf(v, acc[1][nt][j]);
                if (g + 24 < cnt) v = fmaxf(v, acc[1][nt][2 + j]);
                v = fmaxf(v, __shfl_xor_sync(0xffffffffu, v, 4));
                v = fmaxf(v, __shfl_xor_sync(0xffffffffu, v, 8));
                v = fmaxf(v, __shfl_xor_sync(0xffffffffu, v, 16));
                if (g == 0) {
                    int col = chunk * 64 + warp_n * 16 + nt * 8 + 2 * t + j;
                    float o = fmaxf(__fadd_rn(v, __ldg(&b2[col])), 0.0f);
                    out[(size_t)i * DOUT + col] = o;
                }
            }
        }
        if (chunk < 3) cp_wait0();
        __syncthreads();
    }
}

// ---------------- extras: pass-through outputs (pos, float(batch)) ----------------
__global__ void extras_kernel(const float* __restrict__ pos,
                              const int* __restrict__ batch,
                              float* __restrict__ out) {
    int t = blockIdx.x * 256 + threadIdx.x;
    if (t < NPTS * 3) out[NPTS * DOUT + t] = pos[t];
    if (t < NPTS)     out[NPTS * DOUT + NPTS * 3 + t] = (float)batch[t];
}

// ---------------- launch ----------------
extern "C" void kernel_launch(void* const* d_in, const int* in_sizes, int n_in,
                              void* d_out, int out_size) {
    const float* x     = (const float*)d_in[0];
    const float* pos   = (const float*)d_in[1];
    const int*   batch = (const int*)d_in[2];
    const float* W1    = (const float*)d_in[3];
    const float* b1    = (const float*)d_in[4];
    const float* W2    = (const float*)d_in[5];
    const float* b2    = (const float*)d_in[6];
    float* out = (float*)d_out;

    cudaFuncSetAttribute(fused_kernel, cudaFuncAttributeMaxDynamicSharedMemorySize,
                         SMEM_FUSED_BYTES);

    prep_kernel<<<256, 256>>>(W2);
    ball_query_kernel<<<NPTS / 8, 256>>>(pos);
    z_kernel<<<NPTS / 16, 256>>>(x, W1);
    fused_kernel<<<NPTS / 4, 512, SMEM_FUSED_BYTES>>>(pos, W1, b1, b2, out);

    if (out_size > NPTS * DOUT)
        extras_kernel<<<(NPTS * 3 + 255) / 256, 256>>>(pos, batch, out);
}

// round 17
// speedup vs baseline: 1.8210x; 1.5451x over previous
#include <cuda_runtime.h>
#include <cuda_bf16.h>
#include <cstdint>
#include <cfloat>

#define NPTS   16384
#define PCLOUD 2048
#define DIN    128
#define KNBR   32
#define HID    256
#define DOUT   256
#define R2     0.04f

// ---------------- scratch ----------------
__device__ float g_Z[NPTS * HID];              // Z = x @ W1[0:128] (fp32 exact)
__device__ int   g_idx[NPTS * KNBR];
__device__ int   g_cnt[NPTS];
// W2^T split to bf16 hi/lo, stored [o][h] row-major
__device__ __nv_bfloat16 g_Bhi[DOUT * HID];
__device__ __nv_bfloat16 g_Blo[DOUT * HID];

// ---------------- helpers ----------------
__device__ __forceinline__ void cp_async16(uint32_t saddr, const void* gptr) {
    asm volatile("cp.async.cg.shared.global [%0], [%1], 16;" :: "r"(saddr), "l"(gptr));
}
__device__ __forceinline__ void cp_commit() { asm volatile("cp.async.commit_group;"); }
__device__ __forceinline__ void cp_wait1()  { asm volatile("cp.async.wait_group 1;"); }
__device__ __forceinline__ void cp_wait0()  { asm volatile("cp.async.wait_group 0;"); }

// m16n8k16 row.col f32.bf16.bf16.f32 (base PTX, sm_80+; HMMA on Blackwell)
__device__ __forceinline__ void mma16816(float* d, const uint32_t* a, const uint32_t* b) {
    asm volatile(
        "mma.sync.aligned.m16n8k16.row.col.f32.bf16.bf16.f32 "
        "{%0,%1,%2,%3}, {%4,%5,%6,%7}, {%8,%9}, {%0,%1,%2,%3};"
        : "+f"(d[0]), "+f"(d[1]), "+f"(d[2]), "+f"(d[3])
        : "r"(a[0]), "r"(a[1]), "r"(a[2]), "r"(a[3]), "r"(b[0]), "r"(b[1]));
}

// ---------------- kernel 1: ball query (bit-exact, DO NOT TOUCH) ----------------
__global__ void __launch_bounds__(256) ball_query_kernel(const float* __restrict__ pos) {
    __shared__ float sp[PCLOUD * 3];
    __shared__ float sn2[PCLOUD];

    const int blocksPerCloud = PCLOUD / 8;
    const int cloud = blockIdx.x / blocksPerCloud;
    const int base  = cloud * PCLOUD;

    for (int t = threadIdx.x; t < PCLOUD; t += 256) {
        float x = pos[(base + t) * 3 + 0];
        float y = pos[(base + t) * 3 + 1];
        float z = pos[(base + t) * 3 + 2];
        sp[t * 3 + 0] = x; sp[t * 3 + 1] = y; sp[t * 3 + 2] = z;
        sn2[t] = __fadd_rn(__fadd_rn(__fmul_rn(x, x), __fmul_rn(y, y)), __fmul_rn(z, z));
    }
    __syncthreads();

    const int warp = threadIdx.x >> 5;
    const int lane = threadIdx.x & 31;
    const int il   = (blockIdx.x % blocksPerCloud) * 8 + warp;
    const int i    = base + il;

    const float xi = sp[il * 3 + 0], yi = sp[il * 3 + 1], zi = sp[il * 3 + 2];
    const float n2i = sn2[il];

    int cnt = 0;
    for (int jb = 0; jb < PCLOUD / 32 && cnt < KNBR; jb++) {
        const int jl = jb * 32 + lane;
        float dot = __fmul_rn(xi, sp[jl * 3 + 0]);
        dot = __fmaf_rn(yi, sp[jl * 3 + 1], dot);
        dot = __fmaf_rn(zi, sp[jl * 3 + 2], dot);
        float d2 = __fsub_rn(__fadd_rn(n2i, sn2[jl]), __fmul_rn(2.0f, dot));
        bool within = (d2 <= R2);
        unsigned m = __ballot_sync(0xffffffffu, within);
        if (within) {
            int rank = cnt + __popc(m & ((1u << lane) - 1u));
            if (rank < KNBR) g_idx[i * KNBR + rank] = base + jl;
        }
        cnt += __popc(m);
    }
    if (lane == 0) g_cnt[i] = cnt < KNBR ? cnt : KNBR;
}

// ---------------- kernel 2: Z = x @ W1[0:128,:] (fp32 exact) ----------------
__global__ void __launch_bounds__(256) z_kernel(const float* __restrict__ x,
                                                const float* __restrict__ W1) {
    __shared__ __align__(16) float sin_[16][128];
    const int r0 = blockIdx.x * 16;

    for (int t = threadIdx.x; t < 16 * 128; t += 256) {
        int r = t >> 7, f = t & 127;
        sin_[r][f] = x[(r0 + r) * DIN + f];
    }
    __syncthreads();

    const int o = threadIdx.x;
    float acc[16];
#pragma unroll
    for (int r = 0; r < 16; r++) acc[r] = 0.0f;

    for (int f4 = 0; f4 < 32; f4++) {
        const float w0 = W1[(f4 * 4 + 0) * HID + o];
        const float w1 = W1[(f4 * 4 + 1) * HID + o];
        const float w2 = W1[(f4 * 4 + 2) * HID + o];
        const float w3 = W1[(f4 * 4 + 3) * HID + o];
#pragma unroll
        for (int r = 0; r < 16; r++) {
            float4 v = *reinterpret_cast<const float4*>(&sin_[r][f4 * 4]);
            acc[r] += v.x * w0;
            acc[r] += v.y * w1;
            acc[r] += v.z * w2;
            acc[r] += v.w * w3;
        }
    }
#pragma unroll
    for (int r = 0; r < 16; r++) g_Z[(r0 + r) * HID + o] = acc[r];
}

// ---------------- kernel 0b: split W2^T into bf16 hi/lo, [o][h] ----------------
__global__ void __launch_bounds__(256) prep_kernel(const float* __restrict__ W2) {
    int t = blockIdx.x * 256 + threadIdx.x;      // [0, 65536)
    int o = t >> 8, h = t & 255;
    float w = W2[h * DOUT + o];
    __nv_bfloat16 hi = __float2bfloat16(w);
    __nv_bfloat16 lo = __float2bfloat16(__fsub_rn(w, __bfloat162float(hi)));
    g_Bhi[o * HID + h] = hi;
    g_Blo[o * HID + h] = lo;
}

// ---------------- kernel 3: fused h1-build + HMMA GEMM2 + maxpool ----------------
// 4 points/block (128 edge rows), 512 threads = 16 warps = 4 warp_m x 4 warp_n.
// Warp tile: 32 rows x 32 cols  (A 8 regs + B 8 regs -> 8 MMAs per k-step).
// A (h1 hi/lo): [128 rows][264 bf16] padded (132 words/row; 132 % 32 == 4).
// B streamed as [128 out-cols][64 h] quarter-K slabs, stride 36 words, hi+lo,
// double-buffered; slab L+1 issued before computing slab L.
#define A_HI_B   0
#define A_LO_B   67584
#define BBUF_B   135168
#define BBUF_SZ  36864         // one slab: hi (18432) + lo (18432)
#define BLO_OFF  18432
#define W1B_B    (BBUF_B + 2 * BBUF_SZ)     // 208896
#define B1_B     (W1B_B + 3072)             // 211968
#define SMEM_FUSED_BYTES (B1_B + 1024)      // 212992
#define ASTRIDE  132    // words per A row
#define BSTRIDE  36     // words per B slab row

__device__ __forceinline__ void load_B_slab(uint32_t smem_u32, uint32_t bufbase,
                                            int chunk, int q, int tid) {
    // 2048 x 16B: [split(2)][row(128)][u(8)]
    for (int idx = tid; idx < 2048; idx += 512) {
        int split = idx >> 10;
        int r = (idx >> 3) & 127;
        int u = idx & 7;
        const __nv_bfloat16* src =
            (split ? g_Blo : g_Bhi) + (chunk * 128 + r) * HID + q * 64 + u * 8;
        cp_async16(smem_u32 + bufbase + split * BLO_OFF + r * 144 + u * 16, src);
    }
}

__global__ void __launch_bounds__(512, 1) fused_kernel(const float* __restrict__ pos,
                                                       const float* __restrict__ W1,
                                                       const float* __restrict__ b1,
                                                       const float* __restrict__ b2,
                                                       float* __restrict__ out) {
    extern __shared__ __align__(16) unsigned char smem[];
    const uint32_t smem_u32 = (uint32_t)__cvta_generic_to_shared(smem);

    const int tid  = threadIdx.x;
    const int wid  = tid >> 5;
    const int lane = tid & 31;
    const int i0   = blockIdx.x * 4;
    const int warp_m = wid >> 2;        // point within block (32 rows)
    const int warp_n = wid & 3;         // 32-col group within 128-col chunk

    float* w1b = (float*)(smem + W1B_B);
    float* b1s = (float*)(smem + B1_B);

    // preload slab L=0 (chunk 0, q 0) into buf 0; overlap with A build
    load_B_slab(smem_u32, BBUF_B, 0, 0, tid);
    cp_commit();

    for (int c = tid; c < 768; c += 512) w1b[c] = W1[128 * HID + c];
    if (tid < 256) b1s[tid] = b1[tid];
    __syncthreads();

    // phase 1: build A = h1 bf16 hi/lo.  thread -> edge e = tid>>2, h-quarter hq = tid&3.
    {
        const int e  = tid >> 2;
        const int hq = tid & 3;
        const int p  = e >> 5, k = e & 31;
        const int i  = i0 + p;
        const int cnt = g_cnt[i];
        const int hbase = hq * 64;
        const uint32_t rowbase = (uint32_t)e * 528 + (uint32_t)hq * 128;

        if (k < cnt) {
            const int j = g_idx[i * KNBR + k];
            const float rx = __fsub_rn(pos[j * 3 + 0], pos[i * 3 + 0]);
            const float ry = __fsub_rn(pos[j * 3 + 1], pos[i * 3 + 1]);
            const float rz = __fsub_rn(pos[j * 3 + 2], pos[i * 3 + 2]);
            const float* Zr = g_Z + (size_t)j * HID + hbase;
#pragma unroll
            for (int m4 = 0; m4 < 8; m4++) {
                float4 za = *(const float4*)(Zr + m4 * 8);
                float4 zb = *(const float4*)(Zr + m4 * 8 + 4);
                float vs[8] = {za.x, za.y, za.z, za.w, zb.x, zb.y, zb.z, zb.w};
                uint32_t phi[4], plo[4];
#pragma unroll
                for (int u2 = 0; u2 < 4; u2++) {
                    int h0 = hbase + m4 * 8 + u2 * 2;
                    float v0 = vs[u2 * 2 + 0];
                    v0 = fmaf(rx, w1b[0 * 256 + h0], v0);
                    v0 = fmaf(ry, w1b[1 * 256 + h0], v0);
                    v0 = fmaf(rz, w1b[2 * 256 + h0], v0);
                    v0 = __fadd_rn(v0, b1s[h0]);
                    v0 = fmaxf(v0, 0.0f);
                    float v1 = vs[u2 * 2 + 1];
                    v1 = fmaf(rx, w1b[0 * 256 + h0 + 1], v1);
                    v1 = fmaf(ry, w1b[1 * 256 + h0 + 1], v1);
                    v1 = fmaf(rz, w1b[2 * 256 + h0 + 1], v1);
                    v1 = __fadd_rn(v1, b1s[h0 + 1]);
                    v1 = fmaxf(v1, 0.0f);
                    __nv_bfloat16 h0b = __float2bfloat16(v0);
                    __nv_bfloat16 h1b = __float2bfloat16(v1);
                    __nv_bfloat16 l0b = __float2bfloat16(__fsub_rn(v0, __bfloat162float(h0b)));
                    __nv_bfloat16 l1b = __float2bfloat16(__fsub_rn(v1, __bfloat162float(h1b)));
                    __nv_bfloat162 ph; ph.x = h0b; ph.y = h1b;
                    __nv_bfloat162 pl; pl.x = l0b; pl.y = l1b;
                    phi[u2] = *reinterpret_cast<uint32_t*>(&ph);
                    plo[u2] = *reinterpret_cast<uint32_t*>(&pl);
                }
                *(uint4*)(smem + A_HI_B + rowbase + m4 * 16) = make_uint4(phi[0], phi[1], phi[2], phi[3]);
                *(uint4*)(smem + A_LO_B + rowbase + m4 * 16) = make_uint4(plo[0], plo[1], plo[2], plo[3]);
            }
        } else {
            uint4 z4 = make_uint4(0, 0, 0, 0);
#pragma unroll
            for (int m4 = 0; m4 < 8; m4++) {
                *(uint4*)(smem + A_HI_B + rowbase + m4 * 16) = z4;
                *(uint4*)(smem + A_LO_B + rowbase + m4 * 16) = z4;
            }
        }
    }

    const uint32_t* Ahi32 = (const uint32_t*)(smem + A_HI_B);
    const uint32_t* Alo32 = (const uint32_t*)(smem + A_LO_B);

    const int g = lane >> 2, t = lane & 3;
    const int i = i0 + warp_m;
    const int cnt = g_cnt[i];
    const int r0 = warp_m * 32 + g;

    for (int chunk = 0; chunk < 2; chunk++) {
        float acc[2][4][4];
#pragma unroll
        for (int mt = 0; mt < 2; mt++)
#pragma unroll
            for (int nt = 0; nt < 4; nt++)
#pragma unroll
                for (int q = 0; q < 4; q++) acc[mt][nt][q] = 0.0f;

        for (int q = 0; q < 4; q++) {
            const int L = chunk * 4 + q;
            if (L + 1 < 8) {
                // buf^1 was consumed at iteration L-1 (sync at its end guards reuse)
                load_B_slab(smem_u32, BBUF_B + ((L + 1) & 1) * BBUF_SZ,
                            (L + 1) >> 2, (L + 1) & 3, tid);
                cp_commit();
                cp_wait1();               // slab L complete, slab L+1 in flight
            } else {
                cp_wait0();
            }
            __syncthreads();

            const uint32_t bufb = BBUF_B + (L & 1) * BBUF_SZ;
            const uint32_t* Bhi32 = (const uint32_t*)(smem + bufb);
            const uint32_t* Blo32 = (const uint32_t*)(smem + bufb + BLO_OFF);

#pragma unroll
            for (int s = 0; s < 3; s++) {
                const uint32_t* Ai = (s == 2) ? Alo32 : Ahi32;
                const uint32_t* Bi = (s == 1) ? Blo32 : Bhi32;
#pragma unroll
                for (int ks = 0; ks < 4; ks++) {
                    const int kwA = q * 32 + ks * 8 + t;
                    const int kwB = ks * 8 + t;
                    uint32_t a[2][4], b[4][2];
#pragma unroll
                    for (int mt = 0; mt < 2; mt++) {
                        a[mt][0] = Ai[(r0 + mt * 16)     * ASTRIDE + kwA];
                        a[mt][1] = Ai[(r0 + mt * 16 + 8) * ASTRIDE + kwA];
                        a[mt][2] = Ai[(r0 + mt * 16)     * ASTRIDE + kwA + 4];
                        a[mt][3] = Ai[(r0 + mt * 16 + 8) * ASTRIDE + kwA + 4];
                    }
#pragma unroll
                    for (int nt = 0; nt < 4; nt++) {
                        const int br = warp_n * 32 + nt * 8 + g;
                        b[nt][0] = Bi[br * BSTRIDE + kwB];
                        b[nt][1] = Bi[br * BSTRIDE + kwB + 4];
                    }
#pragma unroll
                    for (int mt = 0; mt < 2; mt++)
#pragma unroll
                        for (int nt = 0; nt < 4; nt++)
                            mma16816(acc[mt][nt], a[mt], b[nt]);
                }
            }
            __syncthreads();              // all warps done with buf (L&1)
        }

        // epilogue: warp-local maxpool over 32 edges of point warp_m (mask k>=cnt)
#pragma unroll
        for (int nt = 0; nt < 4; nt++) {
#pragma unroll
            for (int j = 0; j < 2; j++) {
                float v = -FLT_MAX;
                if (g < cnt)      v = fmaxf(v, acc[0][nt][j]);
                if (g + 8 < cnt)  v = fmaxf(v, acc[0][nt][2 + j]);
                if (g + 16 < cnt) v = fmaxf(v, acc[1][nt][j]);
                if (g + 24 < cnt) v = fmaxf(v, acc[1][nt][2 + j]);
                v = fmaxf(v, __shfl_xor_sync(0xffffffffu, v, 4));
                v = fmaxf(v, __shfl_xor_sync(0xffffffffu, v, 8));
                v = fmaxf(v, __shfl_xor_sync(0xffffffffu, v, 16));
                if (g == 0) {
                    int col = chunk * 128 + warp_n * 32 + nt * 8 + 2 * t + j;
                    float o = fmaxf(__fadd_rn(v, __ldg(&b2[col])), 0.0f);
                    out[(size_t)i * DOUT + col] = o;
                }
            }
        }
    }
}

// ---------------- extras: pass-through outputs (pos, float(batch)) ----------------
__global__ void extras_kernel(const float* __restrict__ pos,
                              const int* __restrict__ batch,
                              float* __restrict__ out) {
    int t = blockIdx.x * 256 + threadIdx.x;
    if (t < NPTS * 3) out[NPTS * DOUT + t] = pos[t];
    if (t < NPTS)     out[NPTS * DOUT + NPTS * 3 + t] = (float)batch[t];
}

// ---------------- launch ----------------
extern "C" void kernel_launch(void* const* d_in, const int* in_sizes, int n_in,
                              void* d_out, int out_size) {
    const float* x     = (const float*)d_in[0];
    const float* pos   = (const float*)d_in[1];
    const int*   batch = (const int*)d_in[2];
    const float* W1    = (const float*)d_in[3];
    const float* b1    = (const float*)d_in[4];
    const float* W2    = (const float*)d_in[5];
    const float* b2    = (const float*)d_in[6];
    float* out = (float*)d_out;

    cudaFuncSetAttribute(fused_kernel, cudaFuncAttributeMaxDynamicSharedMemorySize,
                         SMEM_FUSED_BYTES);

    prep_kernel<<<256, 256>>>(W2);
    ball_query_kernel<<<NPTS / 8, 256>>>(pos);
    z_kernel<<<NPTS / 16, 256>>>(x, W1);
    fused_kernel<<<NPTS / 4, 512, SMEM_FUSED_BYTES>>>(pos, W1, b1, b2, out);

    if (out_size > NPTS * DOUT)
        extras_kernel<<<(NPTS * 3 + 255) / 256, 256>>>(pos, batch, out);
}